// round 3
// baseline (speedup 1.0000x reference)
#include <cuda_runtime.h>

#define B_EX   16384
#define NEG    10
#define E_DIM  128
#define WARPS_PER_BLOCK 8
#define THREADS (WARPS_PER_BLOCK * 32)
#define NBLOCKS (B_EX / WARPS_PER_BLOCK)   // 2048

// Scratch (allocation-free __device__ globals per harness rules)
__device__ float        g_partials[NBLOCKS];
__device__ unsigned int g_count = 0;

__device__ __forceinline__ float log_sigmoid(float x) {
    // stable: min(x,0) - log1p(exp(-|x|))
    return fminf(x, 0.0f) - log1pf(expf(-fabsf(x)));
}

__global__ void __launch_bounds__(THREADS)
w2v_fused_kernel(const int*    __restrict__ input_word,
                 const int*    __restrict__ context_word,
                 const int*    __restrict__ noise_words,
                 const float4* __restrict__ W_in,
                 const float4* __restrict__ W_ctx,
                 float*        __restrict__ out)
{
    const int lane    = threadIdx.x & 31;
    const int warp_in = threadIdx.x >> 5;
    const int b       = blockIdx.x * WARPS_PER_BLOCK + warp_in;   // example id

    // Lanes 0..11 each load ONE index into tmp; broadcast from tmp (never
    // overwritten -> no clobber bug).
    int tmp = 0;
    if (lane == 0)                  tmp = input_word[b];
    else if (lane == 1)             tmp = context_word[b];
    else if (lane < 12)             tmp = noise_words[b * NEG + (lane - 2)];

    const int ci = __shfl_sync(0xffffffffu, tmp, 0);
    const int xi = __shfl_sync(0xffffffffu, tmp, 1);
    int nidx[NEG];
#pragma unroll
    for (int k = 0; k < NEG; k++)
        nidx[k] = __shfl_sync(0xffffffffu, tmp, k + 2);

    // Row = 128 floats = 32 float4; lane l owns float4 #l of each row.
    // Issue all 12 gathers before any math for max MLP.
    float4 c = W_in [(size_t)ci * 32 + lane];
    float4 x = W_ctx[(size_t)xi * 32 + lane];
    float4 nv[NEG];
#pragma unroll
    for (int k = 0; k < NEG; k++)
        nv[k] = W_ctx[(size_t)nidx[k] * 32 + lane];

    // Per-lane partial dot products.
    float pos = c.x * x.x + c.y * x.y + c.z * x.z + c.w * x.w;
    float neg[NEG];
#pragma unroll
    for (int k = 0; k < NEG; k++)
        neg[k] = c.x * nv[k].x + c.y * nv[k].y + c.z * nv[k].z + c.w * nv[k].w;

    // Warp reduce 11 values.
#pragma unroll
    for (int off = 16; off > 0; off >>= 1) {
        pos += __shfl_xor_sync(0xffffffffu, pos, off);
#pragma unroll
        for (int k = 0; k < NEG; k++)
            neg[k] += __shfl_xor_sync(0xffffffffu, neg[k], off);
    }

    // Per-example loss: -( ls(pos) + sum_k ls(-neg_k) ), one value per warp.
    __shared__ float s_warp[WARPS_PER_BLOCK];
    if (lane == 0) {
        float v = -log_sigmoid(pos);
#pragma unroll
        for (int k = 0; k < NEG; k++)
            v -= log_sigmoid(-neg[k]);
        s_warp[warp_in] = v;
    }
    __syncthreads();

    if (threadIdx.x == 0) {
        float t = 0.0f;
#pragma unroll
        for (int i = 0; i < WARPS_PER_BLOCK; i++) t += s_warp[i];
        g_partials[blockIdx.x] = t;
    }

    // ---- fused finalize: last block to arrive reduces all partials ----
    __shared__ bool s_is_last;
    __threadfence();                       // make g_partials[blockIdx.x] visible
    if (threadIdx.x == 0) {
        unsigned int v = atomicAdd(&g_count, 1u);
        s_is_last = (v == (unsigned int)(NBLOCKS - 1));
    }
    __syncthreads();

    if (s_is_last) {
        // Fixed-order accumulation -> bitwise deterministic across replays.
        volatile float* gp = g_partials;
        float t = 0.0f;
#pragma unroll
        for (int j = 0; j < NBLOCKS / THREADS; j++)     // 8 iterations
            t += gp[threadIdx.x + j * THREADS];

        __shared__ float s_red[THREADS];
        s_red[threadIdx.x] = t;
        __syncthreads();
#pragma unroll
        for (int step = THREADS / 2; step > 0; step >>= 1) {
            if (threadIdx.x < step) s_red[threadIdx.x] += s_red[threadIdx.x + step];
            __syncthreads();
        }
        if (threadIdx.x == 0) {
            out[0]  = s_red[0] / (float)B_EX;
            g_count = 0;                   // reset for next graph replay
        }
    }
}

extern "C" void kernel_launch(void* const* d_in, const int* in_sizes, int n_in,
                              void* d_out, int out_size)
{
    const int*    input_word   = (const int*)   d_in[0];
    const int*    context_word = (const int*)   d_in[1];
    const int*    noise_words  = (const int*)   d_in[2];
    const float4* W_in         = (const float4*)d_in[3];
    const float4* W_ctx        = (const float4*)d_in[4];
    float* out = (float*)d_out;

    w2v_fused_kernel<<<NBLOCKS, THREADS>>>(input_word, context_word,
                                           noise_words, W_in, W_ctx, out);
}

// round 5
// speedup vs baseline: 1.5333x; 1.5333x over previous
#include <cuda_runtime.h>

#define B_EX   16384
#define NEG    10
#define E_DIM  128
#define WARPS_PER_BLOCK 8
#define THREADS (WARPS_PER_BLOCK * 32)
#define NBLOCKS (B_EX / WARPS_PER_BLOCK)   // 2048

// Scratch (allocation-free __device__ globals per harness rules)
__device__ float        g_partials[NBLOCKS];
__device__ unsigned int g_count = 0;

__device__ __forceinline__ float log_sigmoid(float x) {
    // stable: min(x,0) - log1p(exp(-|x|))
    return fminf(x, 0.0f) - log1pf(expf(-fabsf(x)));
}

__device__ __forceinline__ float warp_sum(float v) {
#pragma unroll
    for (int off = 16; off > 0; off >>= 1)
        v += __shfl_xor_sync(0xffffffffu, v, off);
    return v;
}

__global__ void __launch_bounds__(THREADS)
w2v_fused_kernel(const int*    __restrict__ input_word,
                 const int*    __restrict__ context_word,
                 const int*    __restrict__ noise_words,
                 const float4* __restrict__ W_in,
                 const float4* __restrict__ W_ctx,
                 float*        __restrict__ out)
{
    const int lane    = threadIdx.x & 31;
    const int warp_in = threadIdx.x >> 5;
    const int b       = blockIdx.x * WARPS_PER_BLOCK + warp_in;   // example id

    // Uniform (same-address) index loads: L1-broadcast, no shuffle dependency.
    const int ci = input_word[b];
    const int xi = context_word[b];
    int nidx[NEG];
#pragma unroll
    for (int k = 0; k < NEG; k++) nidx[k] = noise_words[b * NEG + k];

    // Row = 128 floats = 32 float4; lane l owns float4 #l of each row.
    // Issue all 12 gathers before any math for max MLP.
    float4 c = W_in [(size_t)ci * 32 + lane];
    float4 x = W_ctx[(size_t)xi * 32 + lane];
    float4 nv[NEG];
#pragma unroll
    for (int k = 0; k < NEG; k++)
        nv[k] = W_ctx[(size_t)nidx[k] * 32 + lane];

    // Per-lane partial dot products -> warp reductions.
    float pos = warp_sum(c.x * x.x + c.y * x.y + c.z * x.z + c.w * x.w);
    float neg[NEG];
#pragma unroll
    for (int k = 0; k < NEG; k++)
        neg[k] = warp_sum(c.x * nv[k].x + c.y * nv[k].y + c.z * nv[k].z + c.w * nv[k].w);

    // Per-example loss: -( ls(pos) + sum_k ls(-neg_k) ), one value per warp.
    __shared__ float s_warp[WARPS_PER_BLOCK];
    if (lane == 0) {
        float v = -log_sigmoid(pos);
#pragma unroll
        for (int k = 0; k < NEG; k++)
            v -= log_sigmoid(-neg[k]);
        s_warp[warp_in] = v;
    }
    __syncthreads();

    // ---- fused finalize: last block to arrive reduces all partials ----
    __shared__ bool s_is_last;
    if (threadIdx.x == 0) {
        float t = 0.0f;
#pragma unroll
        for (int i = 0; i < WARPS_PER_BLOCK; i++) t += s_warp[i];
        g_partials[blockIdx.x] = t;
        // Release atomic: orders the STG above at L2 — no per-thread
        // MEMBAR.GPU, no L1 invalidate storm (the R3 regression).
        unsigned int v;
        asm volatile("atom.release.gpu.global.add.u32 %0, [%1], 1;"
                     : "=r"(v) : "l"(&g_count) : "memory");
        s_is_last = (v == (unsigned int)(NBLOCKS - 1));
    }
    __syncthreads();

    if (s_is_last) {
        // One acquire fence for the whole kernel (winning block only).
        asm volatile("fence.acquire.gpu;" ::: "memory");
        // Fixed-order accumulation -> bitwise deterministic across replays.
        volatile float* gp = g_partials;    // L1-bypass loads
        float t = 0.0f;
#pragma unroll
        for (int j = 0; j < NBLOCKS / THREADS; j++)     // 8 iterations
            t += gp[threadIdx.x + j * THREADS];

        __shared__ float s_red[THREADS];
        s_red[threadIdx.x] = t;
        __syncthreads();
#pragma unroll
        for (int step = THREADS / 2; step > 0; step >>= 1) {
            if (threadIdx.x < step) s_red[threadIdx.x] += s_red[threadIdx.x + step];
            __syncthreads();
        }
        if (threadIdx.x == 0) {
            out[0]  = s_red[0] / (float)B_EX;
            g_count = 0;                   // reset for next graph replay
        }
    }
}

extern "C" void kernel_launch(void* const* d_in, const int* in_sizes, int n_in,
                              void* d_out, int out_size)
{
    const int*    input_word   = (const int*)   d_in[0];
    const int*    context_word = (const int*)   d_in[1];
    const int*    noise_words  = (const int*)   d_in[2];
    const float4* W_in         = (const float4*)d_in[3];
    const float4* W_ctx        = (const float4*)d_in[4];
    float* out = (float*)d_out;

    w2v_fused_kernel<<<NBLOCKS, THREADS>>>(input_word, context_word,
                                           noise_words, W_in, W_ctx, out);
}